// round 15
// baseline (speedup 1.0000x reference)
#include <cuda_runtime.h>
#include <cuda_fp16.h>
#include <cstdint>

// ---------------------------------------------------------------------------
// Problem dims
// ---------------------------------------------------------------------------
#define N_DIM  8192
#define IN_CH  128
#define OUT_CH 64

// Big-GEMM tiling (mma.sync fp16; tcgen05 unavailable at compute_103)
#define TM       128               // M rows per tile
#define KB       32                // K per stage (fp16 elements)
#define SPLITK   16
#define KSPAN    (N_DIM / SPLITK)  // 512
#define NITER    (KSPAN / KB)      // 16
#define GTHREADS 256               // 8 warps; each warp: 16 rows x 64 cols

// Double-buffered fp16 stages: 64B rows, chunk swizzle c ^= (r>>1)&3.
// Stage: A 8192 | B 4096 = 12288 B; x2 = 24576 B (dynamic).
#define ST_A     0
#define ST_B     8192
#define STAGE    12288
#define DSMEM    24576

// ---------------------------------------------------------------------------
// Scratch (__device__ globals). Referenced ONLY from device code — never
// passed as kernel args from host (that was the R4/R5 bug).
// ---------------------------------------------------------------------------
__device__ __align__(16) float g_part[SPLITK * N_DIM * OUT_CH];  // 32 MB partials
__device__ __align__(16) __half g_bf[OUT_CH * N_DIM];            // B^T fp16, K-major

// ---------------------------------------------------------------------------
// PTX helpers (baseline ISA: ldmatrix + mma.sync; NO cp.async — proven slow)
// ---------------------------------------------------------------------------
__device__ __forceinline__ uint32_t smem_u32(const void* p) {
    uint32_t a;
    asm("{ .reg .u64 t; cvta.to.shared.u64 t, %1; cvt.u32.u64 %0, t; }"
        : "=r"(a) : "l"(p));
    return a;
}
__device__ __forceinline__ void ldsm4(uint32_t* r, uint32_t addr) {
    asm volatile("ldmatrix.sync.aligned.m8n8.x4.shared.b16 {%0,%1,%2,%3}, [%4];"
                 : "=r"(r[0]), "=r"(r[1]), "=r"(r[2]), "=r"(r[3]) : "r"(addr));
}
__device__ __forceinline__ void mma16816(float* c, const uint32_t* a,
                                         uint32_t b0, uint32_t b1) {
    asm volatile(
        "mma.sync.aligned.m16n8k16.row.col.f32.f16.f16.f32 "
        "{%0,%1,%2,%3}, {%4,%5,%6,%7}, {%8,%9}, {%0,%1,%2,%3};"
        : "+f"(c[0]), "+f"(c[1]), "+f"(c[2]), "+f"(c[3])
        : "r"(a[0]), "r"(a[1]), "r"(a[2]), "r"(a[3]), "r"(b0), "r"(b1));
}

// ---------------------------------------------------------------------------
// Kernel 1: g_bf[n][k] = fp16( (features @ W)[k][n] )   — fused transpose.
// ---------------------------------------------------------------------------
__global__ __launch_bounds__(256) void lin_kernel(
    const float* __restrict__ F, const float* __restrict__ W)
{
    __shared__ float Ws[IN_CH][OUT_CH];
    const int tid = threadIdx.x;
    #pragma unroll
    for (int t = 0; t < 8; t++) {
        int idx = tid + t * 256;
        int r = idx >> 4, c4 = idx & 15;
        *reinterpret_cast<float4*>(&Ws[r][c4 * 4]) =
            *reinterpret_cast<const float4*>(&W[r * OUT_CH + c4 * 4]);
    }
    __syncthreads();

    const int row = blockIdx.x * 32 + (tid >> 3);
    const int c0  = (tid & 7) * 8;
    float acc[8];
    #pragma unroll
    for (int j = 0; j < 8; j++) acc[j] = 0.0f;

    #pragma unroll 8
    for (int k = 0; k < IN_CH; k += 4) {
        float4 a4 = *reinterpret_cast<const float4*>(&F[row * IN_CH + k]);
        float av[4] = {a4.x, a4.y, a4.z, a4.w};
        #pragma unroll
        for (int kk = 0; kk < 4; kk++)
            #pragma unroll
            for (int j = 0; j < 8; j++)
                acc[j] = fmaf(av[kk], Ws[k + kk][c0 + j], acc[j]);
    }
    #pragma unroll
    for (int j = 0; j < 8; j++)
        g_bf[(size_t)(c0 + j) * N_DIM + row] = __float2half(acc[j]);
}

// ---------------------------------------------------------------------------
// Kernel 2: fp16 GEMM (mma.sync.m16n8k16), KB=32, double-buffered stages,
//           TWO register staging sets, LDG issued TWO chunks ahead.
//   partial[s] = A[mTile, kspan_s] @ B^T      (B from g_bf)
// ---------------------------------------------------------------------------

// Load chunk it_ into register set s_ (A: 4 float4; B: 1 uint4)
#define LDG_TILE(it_, s_) do {                                                  \
    _Pragma("unroll")                                                           \
    for (int j_ = 0; j_ < 4; j_++)                                              \
        stA[s_][j_] = *reinterpret_cast<const float4*>(                         \
            Ablk + (size_t)aR * N_DIM + (it_) * KB + aH * 16 + j_ * 4);         \
    stB[s_] = *reinterpret_cast<const uint4*>(                                  \
        g_bf + (size_t)bRow * N_DIM + kBase + (it_) * KB + bC * 8);             \
} while (0)

// Convert chunk u_ (register set u_&1) -> fp16 into stage[u_&1]
#define STS_TILE(u_) do {                                                       \
    const int s_ = (u_) & 1;                                                    \
    char* sb_ = sm + s_ * STAGE;                                                \
    _Pragma("unroll")                                                           \
    for (int i_ = 0; i_ < 2; i_++) {       /* 16B chunk from 8 floats */        \
        float4 va_ = stA[s_][i_ * 2], vb_ = stA[s_][i_ * 2 + 1];                \
        uint4 h_;                                                               \
        asm("cvt.rn.f16x2.f32 %0, %1, %2;" : "=r"(h_.x) : "f"(va_.y), "f"(va_.x)); \
        asm("cvt.rn.f16x2.f32 %0, %1, %2;" : "=r"(h_.y) : "f"(va_.w), "f"(va_.z)); \
        asm("cvt.rn.f16x2.f32 %0, %1, %2;" : "=r"(h_.z) : "f"(vb_.y), "f"(vb_.x)); \
        asm("cvt.rn.f16x2.f32 %0, %1, %2;" : "=r"(h_.w) : "f"(vb_.w), "f"(vb_.z)); \
        uint32_t c_   = (uint32_t)(aH * 2 + i_);                                \
        uint32_t off_ = (uint32_t)aR * 64 + ((c_ ^ aXor) << 4);                 \
        *reinterpret_cast<uint4*>(sb_ + ST_A + off_) = h_;                      \
    }                                                                           \
    {                                                                           \
        uint32_t off_ = (uint32_t)bRow * 64 + (((uint32_t)bC ^ bXorS) << 4);    \
        *reinterpret_cast<uint4*>(sb_ + ST_B + off_) = stB[s_];                 \
    }                                                                           \
} while (0)

__global__ __launch_bounds__(GTHREADS, 2) void mma_gemm(const float* __restrict__ A)
{
    extern __shared__ __align__(128) char sm[];
    const uint32_t sbase = smem_u32(sm);

    const int tid = threadIdx.x;
    const int wid = tid >> 5;
    const int lid = tid & 31;
    const int wm  = wid * 16;                 // warp's 16-row slice

    const int mBase = blockIdx.x * TM;
    const int kBase = blockIdx.y * KSPAN;
    const float* Ablk = A + (size_t)mBase * N_DIM + kBase;

    // A staging: row aR = tid>>1, half aH = tid&1 (16 floats -> 2 chunks)
    const int aR = tid >> 1;
    const int aH = tid & 1;
    const uint32_t aXor = (uint32_t)((aR >> 1) & 3);
    // B staging: one chunk per thread: row = tid>>2, chunk = tid&3
    const int bRow = tid >> 2;
    const int bC   = tid & 3;
    const uint32_t bXorS = (uint32_t)((bRow >> 1) & 3);

    float4 stA[2][4];
    uint4  stB[2];

    float acc[8][4];
    #pragma unroll
    for (int t = 0; t < 8; t++)
        #pragma unroll
        for (int j = 0; j < 4; j++) acc[t][j] = 0.0f;

    // per-lane ldmatrix invariants (R10-proven)
    const uint32_t rA    = (uint32_t)(wm + (lid & 15));
    const uint32_t aFXor = (rA >> 1) & 3u;
    const uint32_t aRowB = rA * 64u;
    const uint32_t aSel  = (uint32_t)(lid >> 4);
    const uint32_t rBL   = (uint32_t)((lid & 7) + ((lid >> 4) & 1) * 8);
    const uint32_t bFXor = (rBL >> 1) & 3u;
    const uint32_t bSel  = (uint32_t)((lid >> 3) & 1);

    // ---- prologue: chunks 0 and 1 in flight; stage 0 built ----
    LDG_TILE(0, 0);
    LDG_TILE(1, 1);
    STS_TILE(0);
    __syncthreads();

    for (int it = 0; it < NITER; it++) {
        // issue chunk it+2 into the register set just freed by STS(it)
        if (it + 2 < NITER) LDG_TILE(it + 2, it & 1);

        // compute from stage[it&1]
        const uint32_t so = sbase + (uint32_t)(it & 1) * STAGE;
        #pragma unroll
        for (int ks = 0; ks < 2; ks++) {
            uint32_t a[4];
            {
                uint32_t aOff = (((uint32_t)(ks * 2) + aSel) ^ aFXor) << 4;
                ldsm4(a, so + ST_A + aRowB + aOff);
            }
            uint32_t bOff = (((uint32_t)(ks * 2) + bSel) ^ bFXor) << 4;
            #pragma unroll
            for (int np = 0; np < 4; np++) {
                uint32_t bAddr = so + ST_B + (uint32_t)np * 1024 + rBL * 64 + bOff;
                uint32_t b[4];
                ldsm4(b, bAddr);
                mma16816(acc[np * 2],     a, b[0], b[1]);
                mma16816(acc[np * 2 + 1], a, b[2], b[3]);
            }
        }

        // STS chunk it+1 (loaded at top of iter it-1 -> ~2 compute phases old)
        if (it + 1 < NITER) STS_TILE(it + 1);
        __syncthreads();                      // single barrier per iter
    }

    // ---- epilogue (R10-proven c-fragment layout) ----
    const int g  = lid >> 2;
    const int tg = lid & 3;
    float* part = g_part + (size_t)blockIdx.y * (N_DIM * OUT_CH);
    const int row0 = mBase + wm + g;
    #pragma unroll
    for (int t = 0; t < 8; t++) {
        int col = t * 8 + tg * 2;
        *reinterpret_cast<float2*>(&part[(size_t)row0 * OUT_CH + col]) =
            make_float2(acc[t][0], acc[t][1]);
        *reinterpret_cast<float2*>(&part[(size_t)(row0 + 8) * OUT_CH + col]) =
            make_float2(acc[t][2], acc[t][3]);
    }
}

// ---------------------------------------------------------------------------
// Kernel 3: reduce split-K partials.
//   phase 0: g_bf[n][m] = fp16( filt[m] * sum_s P[s][m][n] )  (fused transpose)
//   phase 1: d_out      = sum_s P[s]
// ---------------------------------------------------------------------------
__global__ __launch_bounds__(256) void reduce_kernel(
    const float* __restrict__ filt, float* __restrict__ outp, int phase)
{
    const int i = blockIdx.x * blockDim.x + threadIdx.x;
    const int stride4 = (N_DIM * OUT_CH) / 4;
    const float4* P = reinterpret_cast<const float4*>(g_part);

    float4 s = P[i];
    #pragma unroll
    for (int sp = 1; sp < SPLITK; sp++) {
        float4 v = P[i + sp * stride4];
        s.x += v.x; s.y += v.y; s.z += v.z; s.w += v.w;
    }
    if (phase == 0) {
        int m = (i * 4) / OUT_CH;
        int c = (i * 4) % OUT_CH;
        float f = filt[m];
        g_bf[(size_t)(c + 0) * N_DIM + m] = __float2half(s.x * f);
        g_bf[(size_t)(c + 1) * N_DIM + m] = __float2half(s.y * f);
        g_bf[(size_t)(c + 2) * N_DIM + m] = __float2half(s.z * f);
        g_bf[(size_t)(c + 3) * N_DIM + m] = __float2half(s.w * f);
    } else {
        reinterpret_cast<float4*>(outp)[i] = s;
    }
}

// ---------------------------------------------------------------------------
// Launch. Inputs: features, weight_matrix, filt, wavelets, wavelets_inv.
// ---------------------------------------------------------------------------
extern "C" void kernel_launch(void* const* d_in, const int* in_sizes, int n_in,
                              void* d_out, int out_size)
{
    const float* features     = (const float*)d_in[0];
    const float* weight       = (const float*)d_in[1];
    const float* filt         = (const float*)d_in[2];
    const float* wavelets     = (const float*)d_in[3];
    const float* wavelets_inv = (const float*)d_in[4];
    float* out = (float*)d_out;

    cudaFuncSetAttribute(mma_gemm,
                         cudaFuncAttributeMaxDynamicSharedMemorySize, DSMEM);

    dim3 grid(N_DIM / TM, SPLITK);                      // (64, 16)
    const int redBlocks = (N_DIM * OUT_CH) / 4 / 256;   // 512

    lin_kernel<<<N_DIM / 32, 256>>>(features, weight);
    mma_gemm<<<grid, GTHREADS, DSMEM>>>(wavelets_inv);
    reduce_kernel<<<redBlocks, 256>>>(filt, nullptr, 0);
    mma_gemm<<<grid, GTHREADS, DSMEM>>>(wavelets);
    reduce_kernel<<<redBlocks, 256>>>(filt, out, 1);
}

// round 16
// speedup vs baseline: 1.3419x; 1.3419x over previous
#include <cuda_runtime.h>
#include <cuda_fp16.h>
#include <cstdint>

// ---------------------------------------------------------------------------
// Problem dims
// ---------------------------------------------------------------------------
#define N_DIM  8192
#define IN_CH  128
#define OUT_CH 64

// Big-GEMM tiling (mma.sync fp16; tcgen05 unavailable at compute_103)
#define TM       128               // M rows per CTA (64 per group)
#define KB       32                // K per stage (fp16 elements)
#define SPLITK   16
#define KSPAN    (N_DIM / SPLITK)  // 512
#define NITER    (KSPAN / KB)      // 16
#define GTHREADS 256               // 2 groups x 4 warps; warp: 16 rows x 64 cols

// Per-group double-buffered stages (64B rows, chunk swizzle c ^= (r>>1)&3):
//   stage: A 64x64B = 4096 | B 64x64B = 4096  -> 8192 B
//   group block: 2 stages = 16384 B ; CTA total 32768 B (dynamic)
#define ST_A     0
#define ST_B     4096
#define STAGE    8192
#define GBLK     16384
#define DSMEM    32768

// ---------------------------------------------------------------------------
// Scratch (__device__ globals). Referenced ONLY from device code — never
// passed as kernel args from host (that was the R4/R5 bug).
// ---------------------------------------------------------------------------
__device__ __align__(16) float g_part[SPLITK * N_DIM * OUT_CH];  // 32 MB partials
__device__ __align__(16) __half g_bf[OUT_CH * N_DIM];            // B^T fp16, K-major

// ---------------------------------------------------------------------------
// PTX helpers (baseline ISA: ldmatrix + mma.sync + named barriers)
// ---------------------------------------------------------------------------
__device__ __forceinline__ uint32_t smem_u32(const void* p) {
    uint32_t a;
    asm("{ .reg .u64 t; cvta.to.shared.u64 t, %1; cvt.u32.u64 %0, t; }"
        : "=r"(a) : "l"(p));
    return a;
}
__device__ __forceinline__ void ldsm4(uint32_t* r, uint32_t addr) {
    asm volatile("ldmatrix.sync.aligned.m8n8.x4.shared.b16 {%0,%1,%2,%3}, [%4];"
                 : "=r"(r[0]), "=r"(r[1]), "=r"(r[2]), "=r"(r[3]) : "r"(addr));
}
__device__ __forceinline__ void mma16816(float* c, const uint32_t* a,
                                         uint32_t b0, uint32_t b1) {
    asm volatile(
        "mma.sync.aligned.m16n8k16.row.col.f32.f16.f16.f32 "
        "{%0,%1,%2,%3}, {%4,%5,%6,%7}, {%8,%9}, {%0,%1,%2,%3};"
        : "+f"(c[0]), "+f"(c[1]), "+f"(c[2]), "+f"(c[3])
        : "r"(a[0]), "r"(a[1]), "r"(a[2]), "r"(a[3]), "r"(b0), "r"(b1));
}
// group barrier: only the 128 threads of group g participate
__device__ __forceinline__ void group_bar(int g) {
    asm volatile("bar.sync %0, %1;" :: "r"(g + 1), "r"(128) : "memory");
}

// ---------------------------------------------------------------------------
// Kernel 1: g_bf[n][k] = fp16( (features @ W)[k][n] )   — fused transpose.
// ---------------------------------------------------------------------------
__global__ __launch_bounds__(256) void lin_kernel(
    const float* __restrict__ F, const float* __restrict__ W)
{
    __shared__ float Ws[IN_CH][OUT_CH];
    const int tid = threadIdx.x;
    #pragma unroll
    for (int t = 0; t < 8; t++) {
        int idx = tid + t * 256;
        int r = idx >> 4, c4 = idx & 15;
        *reinterpret_cast<float4*>(&Ws[r][c4 * 4]) =
            *reinterpret_cast<const float4*>(&W[r * OUT_CH + c4 * 4]);
    }
    __syncthreads();

    const int row = blockIdx.x * 32 + (tid >> 3);
    const int c0  = (tid & 7) * 8;
    float acc[8];
    #pragma unroll
    for (int j = 0; j < 8; j++) acc[j] = 0.0f;

    #pragma unroll 8
    for (int k = 0; k < IN_CH; k += 4) {
        float4 a4 = *reinterpret_cast<const float4*>(&F[row * IN_CH + k]);
        float av[4] = {a4.x, a4.y, a4.z, a4.w};
        #pragma unroll
        for (int kk = 0; kk < 4; kk++)
            #pragma unroll
            for (int j = 0; j < 8; j++)
                acc[j] = fmaf(av[kk], Ws[k + kk][c0 + j], acc[j]);
    }
    #pragma unroll
    for (int j = 0; j < 8; j++)
        g_bf[(size_t)(c0 + j) * N_DIM + row] = __float2half(acc[j]);
}

// ---------------------------------------------------------------------------
// Kernel 2: fp16 GEMM (mma.sync.m16n8k16), KB=32, R10 inner loop, but the
//           CTA is split into TWO independent 4-warp groups (own A half,
//           own B copy, own stages, named-barrier sync) to halve
//           barrier-straggler coupling.
//   partial[s] = A[mTile, kspan_s] @ B^T      (B from g_bf)
// ---------------------------------------------------------------------------

// Load chunk it_ into registers (A: 4 float4; B: 2 uint4 — group-private copy)
#define LDG_TILE(it_) do {                                                      \
    _Pragma("unroll")                                                           \
    for (int j_ = 0; j_ < 4; j_++)                                              \
        stA[j_] = *reinterpret_cast<const float4*>(                             \
            Ablk + (size_t)aR * N_DIM + (it_) * KB + aH * 16 + j_ * 4);         \
    _Pragma("unroll")                                                           \
    for (int j_ = 0; j_ < 2; j_++)                                              \
        stB[j_] = *reinterpret_cast<const uint4*>(                              \
            g_bf + (size_t)bRow * N_DIM + kBase + (it_) * KB + bH * 16 + j_ * 8); \
} while (0)

// Convert + store into the group's stage (u_&1)
#define STS_TILE(u_) do {                                                       \
    char* sb_ = sm + gBase + ((u_) & 1) * STAGE;                                \
    _Pragma("unroll")                                                           \
    for (int i_ = 0; i_ < 2; i_++) {       /* 16B chunk from 8 floats */        \
        float4 va_ = stA[i_ * 2], vb_ = stA[i_ * 2 + 1];                        \
        uint4 h_;                                                               \
        asm("cvt.rn.f16x2.f32 %0, %1, %2;" : "=r"(h_.x) : "f"(va_.y), "f"(va_.x)); \
        asm("cvt.rn.f16x2.f32 %0, %1, %2;" : "=r"(h_.y) : "f"(va_.w), "f"(va_.z)); \
        asm("cvt.rn.f16x2.f32 %0, %1, %2;" : "=r"(h_.z) : "f"(vb_.y), "f"(vb_.x)); \
        asm("cvt.rn.f16x2.f32 %0, %1, %2;" : "=r"(h_.w) : "f"(vb_.w), "f"(vb_.z)); \
        uint32_t c_   = (uint32_t)(aH * 2 + i_);                                \
        uint32_t off_ = (uint32_t)aR * 64 + ((c_ ^ aXor) << 4);                 \
        *reinterpret_cast<uint4*>(sb_ + ST_A + off_) = h_;                      \
    }                                                                           \
    _Pragma("unroll")                                                           \
    for (int j_ = 0; j_ < 2; j_++) {                                            \
        uint32_t c_   = (uint32_t)(bH * 2 + j_);                                \
        uint32_t off_ = (uint32_t)bRow * 64 + ((c_ ^ bXorS) << 4);              \
        *reinterpret_cast<uint4*>(sb_ + ST_B + off_) = stB[j_];                 \
    }                                                                           \
} while (0)

__global__ __launch_bounds__(GTHREADS, 3) void mma_gemm(const float* __restrict__ A)
{
    extern __shared__ __align__(128) char sm[];
    const uint32_t sbase = smem_u32(sm);

    const int tid = threadIdx.x;
    const int wid = tid >> 5;
    const int lid = tid & 31;
    const int grp = tid >> 7;                 // group 0/1 (warps 0-3 / 4-7)
    const int tg  = tid & 127;                // thread-in-group
    const int wg  = (wid & 3) * 16;           // warp's 16-row slice in group
    const uint32_t gBase = (uint32_t)grp * GBLK;

    const int mBase = blockIdx.x * TM;
    const int kBase = blockIdx.y * KSPAN;
    // group's 64 A rows start at mBase + grp*64
    const float* Ablk = A + (size_t)(mBase + grp * 64) * N_DIM + kBase;

    // A staging (group-local): row aR = tg>>1 (0..63), half aH = tg&1
    const int aR = tg >> 1;
    const int aH = tg & 1;
    const uint32_t aXor = (uint32_t)((aR >> 1) & 3);
    // B staging (group-private full copy): row = tg>>1, half bH = tg&1 (32B)
    const int bRow = tg >> 1;
    const int bH   = tg & 1;
    const uint32_t bXorS = (uint32_t)((bRow >> 1) & 3);

    float4 stA[4];
    uint4  stB[2];

    float acc[8][4];
    #pragma unroll
    for (int t = 0; t < 8; t++)
        #pragma unroll
        for (int j = 0; j < 4; j++) acc[t][j] = 0.0f;

    // per-lane ldmatrix invariants (rows are group-local 0..63)
    const uint32_t rA    = (uint32_t)(wg + (lid & 15));
    const uint32_t aFXor = (rA >> 1) & 3u;
    const uint32_t aRowB = rA * 64u;
    const uint32_t aSel  = (uint32_t)(lid >> 4);
    const uint32_t rBL   = (uint32_t)((lid & 7) + ((lid >> 4) & 1) * 8);
    const uint32_t bFXor = (rBL >> 1) & 3u;
    const uint32_t bSel  = (uint32_t)((lid >> 3) & 1);

    // ---- prologue: stage 0 built; chunk 1 in flight ----
    LDG_TILE(0);
    STS_TILE(0);
    LDG_TILE(1);
    group_bar(grp);

    for (int it = 0; it < NITER; it++) {
        const uint32_t so = sbase + gBase + (uint32_t)(it & 1) * STAGE;

        // compute from group stage[it&1]
        #pragma unroll
        for (int ks = 0; ks < 2; ks++) {
            uint32_t a[4];
            {
                uint32_t aOff = (((uint32_t)(ks * 2) + aSel) ^ aFXor) << 4;
                ldsm4(a, so + ST_A + aRowB + aOff);
            }
            uint32_t bOff = (((uint32_t)(ks * 2) + bSel) ^ bFXor) << 4;
            #pragma unroll
            for (int np = 0; np < 4; np++) {
                uint32_t bAddr = so + ST_B + (uint32_t)np * 1024 + rBL * 64 + bOff;
                uint32_t b[4];
                ldsm4(b, bAddr);
                mma16816(acc[np * 2],     a, b[0], b[1]);
                mma16816(acc[np * 2 + 1], a, b[2], b[3]);
            }
        }

        // STS chunk it+1 into the other stage; refill regs with chunk it+2
        if (it + 1 < NITER) {
            STS_TILE(it + 1);
            if (it + 2 < NITER) LDG_TILE(it + 2);
        }
        group_bar(grp);                       // only this group's 4 warps
    }

    // ---- epilogue (R10-proven c-fragment layout) ----
    const int g  = lid >> 2;
    const int tgc = lid & 3;
    float* part = g_part + (size_t)blockIdx.y * (N_DIM * OUT_CH);
    const int row0 = mBase + grp * 64 + wg + g;
    #pragma unroll
    for (int t = 0; t < 8; t++) {
        int col = t * 8 + tgc * 2;
        *reinterpret_cast<float2*>(&part[(size_t)row0 * OUT_CH + col]) =
            make_float2(acc[t][0], acc[t][1]);
        *reinterpret_cast<float2*>(&part[(size_t)(row0 + 8) * OUT_CH + col]) =
            make_float2(acc[t][2], acc[t][3]);
    }
}

// ---------------------------------------------------------------------------
// Kernel 3: reduce split-K partials.
//   phase 0: g_bf[n][m] = fp16( filt[m] * sum_s P[s][m][n] )  (fused transpose)
//   phase 1: d_out      = sum_s P[s]
// ---------------------------------------------------------------------------
__global__ __launch_bounds__(256) void reduce_kernel(
    const float* __restrict__ filt, float* __restrict__ outp, int phase)
{
    const int i = blockIdx.x * blockDim.x + threadIdx.x;
    const int stride4 = (N_DIM * OUT_CH) / 4;
    const float4* P = reinterpret_cast<const float4*>(g_part);

    float4 s = P[i];
    #pragma unroll
    for (int sp = 1; sp < SPLITK; sp++) {
        float4 v = P[i + sp * stride4];
        s.x += v.x; s.y += v.y; s.z += v.z; s.w += v.w;
    }
    if (phase == 0) {
        int m = (i * 4) / OUT_CH;
        int c = (i * 4) % OUT_CH;
        float f = filt[m];
        g_bf[(size_t)(c + 0) * N_DIM + m] = __float2half(s.x * f);
        g_bf[(size_t)(c + 1) * N_DIM + m] = __float2half(s.y * f);
        g_bf[(size_t)(c + 2) * N_DIM + m] = __float2half(s.z * f);
        g_bf[(size_t)(c + 3) * N_DIM + m] = __float2half(s.w * f);
    } else {
        reinterpret_cast<float4*>(outp)[i] = s;
    }
}

// ---------------------------------------------------------------------------
// Launch. Inputs: features, weight_matrix, filt, wavelets, wavelets_inv.
// ---------------------------------------------------------------------------
extern "C" void kernel_launch(void* const* d_in, const int* in_sizes, int n_in,
                              void* d_out, int out_size)
{
    const float* features     = (const float*)d_in[0];
    const float* weight       = (const float*)d_in[1];
    const float* filt         = (const float*)d_in[2];
    const float* wavelets     = (const float*)d_in[3];
    const float* wavelets_inv = (const float*)d_in[4];
    float* out = (float*)d_out;

    cudaFuncSetAttribute(mma_gemm,
                         cudaFuncAttributeMaxDynamicSharedMemorySize, DSMEM);

    dim3 grid(N_DIM / TM, SPLITK);                      // (64, 16)
    const int redBlocks = (N_DIM * OUT_CH) / 4 / 256;   // 512

    lin_kernel<<<N_DIM / 32, 256>>>(features, weight);
    mma_gemm<<<grid, GTHREADS, DSMEM>>>(wavelets_inv);
    reduce_kernel<<<redBlocks, 256>>>(filt, nullptr, 0);
    mma_gemm<<<grid, GTHREADS, DSMEM>>>(wavelets);
    reduce_kernel<<<redBlocks, 256>>>(filt, out, 1);
}

// round 17
// speedup vs baseline: 1.4435x; 1.0758x over previous
#include <cuda_runtime.h>
#include <cuda_fp16.h>
#include <cstdint>

// ---------------------------------------------------------------------------
// Problem dims
// ---------------------------------------------------------------------------
#define N_DIM  8192
#define IN_CH  128
#define OUT_CH 64

// Big-GEMM tiling (mma.sync fp16; tcgen05 unavailable at compute_103)
#define TM       128               // M rows per tile
#define KB       32                // K per stage (fp16 elements)
#define SPLITK   16
#define KSPAN    (N_DIM / SPLITK)  // 512
#define NITER    (KSPAN / KB)      // 16
#define GTHREADS 256               // 8 warps; each warp: 16 rows x 64 cols

// FOUR-deep fp16 stages: 64B rows, chunk swizzle c ^= (r>>1)&3.
// Stage: A 8192 | B 4096 = 12288 B; x4 = 49152 B (dynamic).
// Barrier only every 2 iterations (reuse distance 4 makes this safe).
#define ST_A     0
#define ST_B     8192
#define STAGE    12288
#define DSMEM    49152

// ---------------------------------------------------------------------------
// Scratch (__device__ globals). Referenced ONLY from device code — never
// passed as kernel args from host (that was the R4/R5 bug).
// ---------------------------------------------------------------------------
__device__ __align__(16) float g_part[SPLITK * N_DIM * OUT_CH];  // 32 MB partials
__device__ __align__(16) __half g_bf[OUT_CH * N_DIM];            // B^T fp16, K-major

// ---------------------------------------------------------------------------
// PTX helpers (baseline ISA: ldmatrix + mma.sync; NO cp.async — proven slow)
// ---------------------------------------------------------------------------
__device__ __forceinline__ uint32_t smem_u32(const void* p) {
    uint32_t a;
    asm("{ .reg .u64 t; cvta.to.shared.u64 t, %1; cvt.u32.u64 %0, t; }"
        : "=r"(a) : "l"(p));
    return a;
}
__device__ __forceinline__ void ldsm4(uint32_t* r, uint32_t addr) {
    asm volatile("ldmatrix.sync.aligned.m8n8.x4.shared.b16 {%0,%1,%2,%3}, [%4];"
                 : "=r"(r[0]), "=r"(r[1]), "=r"(r[2]), "=r"(r[3]) : "r"(addr));
}
__device__ __forceinline__ void mma16816(float* c, const uint32_t* a,
                                         uint32_t b0, uint32_t b1) {
    asm volatile(
        "mma.sync.aligned.m16n8k16.row.col.f32.f16.f16.f32 "
        "{%0,%1,%2,%3}, {%4,%5,%6,%7}, {%8,%9}, {%0,%1,%2,%3};"
        : "+f"(c[0]), "+f"(c[1]), "+f"(c[2]), "+f"(c[3])
        : "r"(a[0]), "r"(a[1]), "r"(a[2]), "r"(a[3]), "r"(b0), "r"(b1));
}

// ---------------------------------------------------------------------------
// Kernel 1: g_bf[n][k] = fp16( (features @ W)[k][n] )   — fused transpose.
// ---------------------------------------------------------------------------
__global__ __launch_bounds__(256) void lin_kernel(
    const float* __restrict__ F, const float* __restrict__ W)
{
    __shared__ float Ws[IN_CH][OUT_CH];
    const int tid = threadIdx.x;
    #pragma unroll
    for (int t = 0; t < 8; t++) {
        int idx = tid + t * 256;
        int r = idx >> 4, c4 = idx & 15;
        *reinterpret_cast<float4*>(&Ws[r][c4 * 4]) =
            *reinterpret_cast<const float4*>(&W[r * OUT_CH + c4 * 4]);
    }
    __syncthreads();

    const int row = blockIdx.x * 32 + (tid >> 3);
    const int c0  = (tid & 7) * 8;
    float acc[8];
    #pragma unroll
    for (int j = 0; j < 8; j++) acc[j] = 0.0f;

    #pragma unroll 8
    for (int k = 0; k < IN_CH; k += 4) {
        float4 a4 = *reinterpret_cast<const float4*>(&F[row * IN_CH + k]);
        float av[4] = {a4.x, a4.y, a4.z, a4.w};
        #pragma unroll
        for (int kk = 0; kk < 4; kk++)
            #pragma unroll
            for (int j = 0; j < 8; j++)
                acc[j] = fmaf(av[kk], Ws[k + kk][c0 + j], acc[j]);
    }
    #pragma unroll
    for (int j = 0; j < 8; j++)
        g_bf[(size_t)(c0 + j) * N_DIM + row] = __float2half(acc[j]);
}

// ---------------------------------------------------------------------------
// Kernel 2: fp16 GEMM (mma.sync.m16n8k16), KB=32. R10 inner loop verbatim,
//           but 4 SMEM stages + barrier every 2 iterations (half the syncs;
//           warps decouple within each barrier pair).
//   partial[s] = A[mTile, kspan_s] @ B^T      (B from g_bf)
// ---------------------------------------------------------------------------

// Load chunk it_ into registers (A: 4 float4; B: 1 uint4) — R10 verbatim
#define LDG_TILE(it_) do {                                                      \
    _Pragma("unroll")                                                           \
    for (int j_ = 0; j_ < 4; j_++)                                              \
        stA[j_] = *reinterpret_cast<const float4*>(                             \
            Ablk + (size_t)aR * N_DIM + (it_) * KB + aH * 16 + j_ * 4);         \
    stB = *reinterpret_cast<const uint4*>(                                      \
        g_bf + (size_t)bRow * N_DIM + kBase + (it_) * KB + bC * 8);             \
} while (0)

// Convert fp32 -> fp16, store chunk u_ into stage[u_&3] — R10 verbatim + &3
#define STS_TILE(u_) do {                                                       \
    char* sb_ = sm + ((u_) & 3) * STAGE;                                        \
    _Pragma("unroll")                                                           \
    for (int i_ = 0; i_ < 2; i_++) {       /* 16B chunk from 8 floats */        \
        float4 va_ = stA[i_ * 2], vb_ = stA[i_ * 2 + 1];                        \
        uint4 h_;                                                               \
        asm("cvt.rn.f16x2.f32 %0, %1, %2;" : "=r"(h_.x) : "f"(va_.y), "f"(va_.x)); \
        asm("cvt.rn.f16x2.f32 %0, %1, %2;" : "=r"(h_.y) : "f"(va_.w), "f"(va_.z)); \
        asm("cvt.rn.f16x2.f32 %0, %1, %2;" : "=r"(h_.z) : "f"(vb_.y), "f"(vb_.x)); \
        asm("cvt.rn.f16x2.f32 %0, %1, %2;" : "=r"(h_.w) : "f"(vb_.w), "f"(vb_.z)); \
        uint32_t c_   = (uint32_t)(aH * 2 + i_);                                \
        uint32_t off_ = (uint32_t)aR * 64 + ((c_ ^ aXor) << 4);                 \
        *reinterpret_cast<uint4*>(sb_ + ST_A + off_) = h_;                      \
    }                                                                           \
    {                                                                           \
        uint32_t off_ = (uint32_t)bRow * 64 + (((uint32_t)bC ^ bXorS) << 4);    \
        *reinterpret_cast<uint4*>(sb_ + ST_B + off_) = stB;                     \
    }                                                                           \
} while (0)

__global__ __launch_bounds__(GTHREADS, 3) void mma_gemm(const float* __restrict__ A)
{
    extern __shared__ __align__(128) char sm[];
    const uint32_t sbase = smem_u32(sm);

    const int tid = threadIdx.x;
    const int wid = tid >> 5;
    const int lid = tid & 31;
    const int wm  = wid * 16;                 // warp's 16-row slice

    const int mBase = blockIdx.x * TM;
    const int kBase = blockIdx.y * KSPAN;
    const float* Ablk = A + (size_t)mBase * N_DIM + kBase;

    // A staging: row aR = tid>>1, half aH = tid&1 (16 floats -> 2 chunks)
    const int aR = tid >> 1;
    const int aH = tid & 1;
    const uint32_t aXor = (uint32_t)((aR >> 1) & 3);
    // B staging: one chunk per thread: row = tid>>2, chunk = tid&3
    const int bRow = tid >> 2;
    const int bC   = tid & 3;
    const uint32_t bXorS = (uint32_t)((bRow >> 1) & 3);

    float4 stA[4];
    uint4  stB;

    float acc[8][4];
    #pragma unroll
    for (int t = 0; t < 8; t++)
        #pragma unroll
        for (int j = 0; j < 4; j++) acc[t][j] = 0.0f;

    // per-lane ldmatrix invariants (R10-proven)
    const uint32_t rA    = (uint32_t)(wm + (lid & 15));
    const uint32_t aFXor = (rA >> 1) & 3u;
    const uint32_t aRowB = rA * 64u;
    const uint32_t aSel  = (uint32_t)(lid >> 4);
    const uint32_t rBL   = (uint32_t)((lid & 7) + ((lid >> 4) & 1) * 8);
    const uint32_t bFXor = (rBL >> 1) & 3u;
    const uint32_t bSel  = (uint32_t)((lid >> 3) & 1);

    // ---- prologue: stages 0 and 1 built; one barrier ----
    LDG_TILE(0);
    STS_TILE(0);
    LDG_TILE(1);                 // regs freed by STS_TILE(0) (in-order issue)
    STS_TILE(1);
    __syncthreads();

    for (int it = 0; it < NITER; it++) {
        // top: issue LDG for chunk it+2 (stage (it+2)&3, last read at it-2)
        if (it + 2 < NITER) LDG_TILE(it + 2);

        // compute from stage[it&3]
        const uint32_t so = sbase + (uint32_t)(it & 3) * STAGE;
        #pragma unroll
        for (int ks = 0; ks < 2; ks++) {
            uint32_t a[4];
            {
                uint32_t aOff = (((uint32_t)(ks * 2) + aSel) ^ aFXor) << 4;
                ldsm4(a, so + ST_A + aRowB + aOff);
            }
            uint32_t bOff = (((uint32_t)(ks * 2) + bSel) ^ bFXor) << 4;
            #pragma unroll
            for (int np = 0; np < 4; np++) {
                uint32_t bAddr = so + ST_B + (uint32_t)np * 1024 + rBL * 64 + bOff;
                uint32_t b[4];
                ldsm4(b, bAddr);
                mma16816(acc[np * 2],     a, b[0], b[1]);
                mma16816(acc[np * 2 + 1], a, b[2], b[3]);
            }
        }

        // bottom: store chunk it+2 into its stage
        if (it + 2 < NITER) STS_TILE(it + 2);

        // barrier only after odd iterations (reuse distance 4 keeps it safe)
        if (it & 1) __syncthreads();
    }

    // ---- epilogue (R10-proven c-fragment layout) ----
    const int g  = lid >> 2;
    const int tg = lid & 3;
    float* part = g_part + (size_t)blockIdx.y * (N_DIM * OUT_CH);
    const int row0 = mBase + wm + g;
    #pragma unroll
    for (int t = 0; t < 8; t++) {
        int col = t * 8 + tg * 2;
        *reinterpret_cast<float2*>(&part[(size_t)row0 * OUT_CH + col]) =
            make_float2(acc[t][0], acc[t][1]);
        *reinterpret_cast<float2*>(&part[(size_t)(row0 + 8) * OUT_CH + col]) =
            make_float2(acc[t][2], acc[t][3]);
    }
}

// ---------------------------------------------------------------------------
// Kernel 3: reduce split-K partials.
//   phase 0: g_bf[n][m] = fp16( filt[m] * sum_s P[s][m][n] )  (fused transpose)
//   phase 1: d_out      = sum_s P[s]
// ---------------------------------------------------------------------------
__global__ __launch_bounds__(256) void reduce_kernel(
    const float* __restrict__ filt, float* __restrict__ outp, int phase)
{
    const int i = blockIdx.x * blockDim.x + threadIdx.x;
    const int stride4 = (N_DIM * OUT_CH) / 4;
    const float4* P = reinterpret_cast<const float4*>(g_part);

    float4 s = P[i];
    #pragma unroll
    for (int sp = 1; sp < SPLITK; sp++) {
        float4 v = P[i + sp * stride4];
        s.x += v.x; s.y += v.y; s.z += v.z; s.w += v.w;
    }
    if (phase == 0) {
        int m = (i * 4) / OUT_CH;
        int c = (i * 4) % OUT_CH;
        float f = filt[m];
        g_bf[(size_t)(c + 0) * N_DIM + m] = __float2half(s.x * f);
        g_bf[(size_t)(c + 1) * N_DIM + m] = __float2half(s.y * f);
        g_bf[(size_t)(c + 2) * N_DIM + m] = __float2half(s.z * f);
        g_bf[(size_t)(c + 3) * N_DIM + m] = __float2half(s.w * f);
    } else {
        reinterpret_cast<float4*>(outp)[i] = s;
    }
}

// ---------------------------------------------------------------------------
// Launch. Inputs: features, weight_matrix, filt, wavelets, wavelets_inv.
// ---------------------------------------------------------------------------
extern "C" void kernel_launch(void* const* d_in, const int* in_sizes, int n_in,
                              void* d_out, int out_size)
{
    const float* features     = (const float*)d_in[0];
    const float* weight       = (const float*)d_in[1];
    const float* filt         = (const float*)d_in[2];
    const float* wavelets     = (const float*)d_in[3];
    const float* wavelets_inv = (const float*)d_in[4];
    float* out = (float*)d_out;

    cudaFuncSetAttribute(mma_gemm,
                         cudaFuncAttributeMaxDynamicSharedMemorySize, DSMEM);

    dim3 grid(N_DIM / TM, SPLITK);                      // (64, 16)
    const int redBlocks = (N_DIM * OUT_CH) / 4 / 256;   // 512

    lin_kernel<<<N_DIM / 32, 256>>>(features, weight);
    mma_gemm<<<grid, GTHREADS, DSMEM>>>(wavelets_inv);
    reduce_kernel<<<redBlocks, 256>>>(filt, nullptr, 0);
    mma_gemm<<<grid, GTHREADS, DSMEM>>>(wavelets);
    reduce_kernel<<<redBlocks, 256>>>(filt, out, 1);
}